// round 3
// baseline (speedup 1.0000x reference)
#include <cuda_runtime.h>
#include <cstdint>
#include <cstddef>

// Problem constants
#define Bv    4
#define CINc  64
#define COUTc 64
#define Nn    16384
#define Kk    8
#define TILE  128
#define TPB   512

// Channel-major scatter scratch: [B][N][COUT] as float4 chunks [B][N][16]
__device__ __align__(16) float4 g_scratch[(size_t)Bv * Nn * (COUTc / 4)];

// ---- PTX helpers -----------------------------------------------------------

// packed dual-FMA: 2x fp32 MAC per instruction (FFMA2 — ptxas won't auto-fuse)
__device__ __forceinline__ void fma2(unsigned long long &acc,
                                     unsigned long long a,
                                     unsigned long long b) {
    asm("fma.rn.f32x2 %0, %1, %2, %0;" : "+l"(acc) : "l"(a), "l"(b));
}
__device__ __forceinline__ unsigned long long pk2(float v) {
    unsigned long long r;
    asm("mov.b64 %0, {%1, %1};" : "=l"(r) : "f"(v));
    return r;
}
__device__ __forceinline__ float2 up2(unsigned long long v) {
    float2 r;
    asm("mov.b64 {%0, %1}, %2;" : "=f"(r.x), "=f"(r.y) : "l"(v));
    return r;
}
// 128-bit vector reduction (sm_90+): one op scatters 4 contiguous floats
__device__ __forceinline__ void red4(float* p, float a, float b, float c, float d) {
    asm volatile("red.global.add.v4.f32 [%0], {%1, %2, %3, %4};"
                 :: "l"(p), "f"(a), "f"(b), "f"(c), "f"(d) : "memory");
}

// ---- Kernel 1: zero the scatter scratch ------------------------------------

__global__ void zero_kernel() {
    size_t i = (size_t)blockIdx.x * blockDim.x + threadIdx.x;
    g_scratch[i] = make_float4(0.f, 0.f, 0.f, 0.f);
}

// ---- Kernel 2: fused GEMM + neighbor scatter --------------------------------
//
// grid = B * (N/TILE) = 512 blocks, 512 threads.
// Per block: one batch b, points [n0, n0+128).
// smem: sW [64i][4d][64o] (64KB) | sF [64i][128p] (32KB)
//       sJ [8k][128p] (4KB)      | sD [3d][8k][128p] (12KB)   => 114688 B
// Thread mapping: group = tid/16 owns points p0..p0+3 (p0 = 4*group);
// lane-in-group lig owns output channels 4*lig..4*lig+3.

__global__ void __launch_bounds__(TPB, 1) flexconv_main(
    const float* __restrict__ feat,   // [B][Cin][N]
    const float* __restrict__ wt,     // [3][Cin][Cout]
    const float* __restrict__ wb,     // [Cin][Cout]
    const int*   __restrict__ nbh,    // [B][K][N]
    const float* __restrict__ pos)    // [B][3][N]
{
    extern __shared__ float sm[];
    float* sW = sm;                    // 16384 floats
    float* sF = sm + 16384;            // 8192 floats
    int*   sJ = (int*)(sm + 24576);    // 1024 ints
    float* sD = sm + 25600;            // 3072 floats

    const int tid = threadIdx.x;
    const int b   = blockIdx.x >> 7;            // N/TILE = 128 tiles per batch
    const int n0  = (blockIdx.x & 127) * TILE;

    // --- stage weights: theta [d][i][o] -> sW[i*256 + d*64 + o]
    #pragma unroll
    for (int t = tid; t < 3 * 64 * 64; t += TPB) {
        int d = t >> 12, i = (t >> 6) & 63, o = t & 63;
        sW[i * 256 + d * 64 + o] = wt[t];
    }
    // bias-weight goes in slot d=3
    #pragma unroll
    for (int t = tid; t < 64 * 64; t += TPB) {
        sW[(t >> 6) * 256 + 192 + (t & 63)] = wb[t];
    }
    // --- stage feature tile: sF[i][p]
    {
        const float* fsrc = feat + (size_t)b * CINc * Nn + n0;
        #pragma unroll
        for (int t = tid; t < 64 * TILE; t += TPB) {
            int i = t >> 7, p = t & 127;
            sF[t] = fsrc[(size_t)i * Nn + p];
        }
    }
    // --- stage neighborhood indices + position deltas
    {
        const float* px = pos + (size_t)b * 3 * Nn;
        const float* py = px + Nn;
        const float* pz = py + Nn;
        const int*   nb = nbh + (size_t)b * Kk * Nn + n0;
        #pragma unroll
        for (int t = tid; t < Kk * TILE; t += TPB) {
            int k = t >> 7, p = t & 127;
            int n = n0 + p;
            int j = nb[(size_t)k * Nn + p];
            sJ[t]        = j;
            sD[t]        = px[j] - px[n];
            sD[1024 + t] = py[j] - py[n];
            sD[2048 + t] = pz[j] - pz[n];
        }
    }
    __syncthreads();

    const int grp = tid >> 4;
    const int lig = tid & 15;
    const int p0  = grp * 4;

    // accumulators: [point q][dim d (x,y,z,bias)][2x packed f32]
    unsigned long long acc[4][4][2];
    #pragma unroll
    for (int q = 0; q < 4; q++)
        #pragma unroll
        for (int d = 0; d < 4; d++) { acc[q][d][0] = 0ull; acc[q][d][1] = 0ull; }

    // --- dense phase: ft[d][o] = sum_i W[d][i][o] * f[i][n], 4 points at once
    #pragma unroll 2
    for (int i = 0; i < 64; i++) {
        const ulonglong2* wrow = (const ulonglong2*)(sW + i * 256);
        ulonglong2 w0 = wrow[lig];        // d=0 (x), channels 4*lig..+3
        ulonglong2 w1 = wrow[16 + lig];   // d=1 (y)
        ulonglong2 w2 = wrow[32 + lig];   // d=2 (z)
        ulonglong2 w3 = wrow[48 + lig];   // d=3 (bias weight)
        float4 fv = *(const float4*)(sF + i * TILE + p0);
        unsigned long long f[4] = { pk2(fv.x), pk2(fv.y), pk2(fv.z), pk2(fv.w) };
        #pragma unroll
        for (int q = 0; q < 4; q++) {
            fma2(acc[q][0][0], w0.x, f[q]); fma2(acc[q][0][1], w0.y, f[q]);
            fma2(acc[q][1][0], w1.x, f[q]); fma2(acc[q][1][1], w1.y, f[q]);
            fma2(acc[q][2][0], w2.x, f[q]); fma2(acc[q][2][1], w2.y, f[q]);
            fma2(acc[q][3][0], w3.x, f[q]); fma2(acc[q][3][1], w3.y, f[q]);
        }
    }

    // --- scatter phase: contrib[o] = fb[o] + dx*ftx[o] + dy*fty[o] + dz*ftz[o]
    #pragma unroll
    for (int q = 0; q < 4; q++) {
        int p = p0 + q;
        float2 x01 = up2(acc[q][0][0]), x23 = up2(acc[q][0][1]);
        float2 y01 = up2(acc[q][1][0]), y23 = up2(acc[q][1][1]);
        float2 z01 = up2(acc[q][2][0]), z23 = up2(acc[q][2][1]);
        float2 w01 = up2(acc[q][3][0]), w23 = up2(acc[q][3][1]);
        #pragma unroll
        for (int k = 0; k < 8; k++) {
            int   j  = sJ[k * TILE + p];
            float dx = sD[k * TILE + p];
            float dy = sD[1024 + k * TILE + p];
            float dz = sD[2048 + k * TILE + p];
            float v0 = w01.x + dx * x01.x + dy * y01.x + dz * z01.x;
            float v1 = w01.y + dx * x01.y + dy * y01.y + dz * z01.y;
            float v2 = w23.x + dx * x23.x + dy * y23.x + dz * z23.x;
            float v3 = w23.y + dx * x23.y + dy * y23.y + dz * z23.y;
            float* dst = (float*)&g_scratch[((size_t)b * Nn + j) * 16 + lig];
            red4(dst, v0, v1, v2, v3);
        }
    }
}

// ---- Kernel 3: transpose scratch [B][N][Cout] -> out [B][Cout][N], add bias --

__global__ void finalize_kernel(float* __restrict__ out, const float* __restrict__ bias) {
    __shared__ float s[64][65];
    const int b   = blockIdx.x >> 8;          // 256 tiles of 64 points per batch
    const int n0  = (blockIdx.x & 255) * 64;
    const int tid = threadIdx.x;              // 256 threads

    const float4* src = (const float4*)g_scratch + ((size_t)b * Nn + n0) * 16;
    #pragma unroll
    for (int r = 0; r < 4; r++) {
        int idx = r * 256 + tid;              // linear over [p(64)][c4(16)]
        float4 v = src[idx];
        int p = idx >> 4, c = (idx & 15) * 4;
        s[p][c] = v.x; s[p][c + 1] = v.y; s[p][c + 2] = v.z; s[p][c + 3] = v.w;
    }
    __syncthreads();
    #pragma unroll
    for (int r = 0; r < 16; r++) {
        int idx = r * 256 + tid;              // [o(64)][p(64)]
        int o = idx >> 6, p = idx & 63;
        out[((size_t)b * 64 + o) * Nn + n0 + p] = s[p][o] + bias[o];
    }
}

// ---- launch -----------------------------------------------------------------

extern "C" void kernel_launch(void* const* d_in, const int* in_sizes, int n_in,
                              void* d_out, int out_size) {
    const float* feat = (const float*)d_in[0];   // features   [4,64,16384]
    const float* wt   = (const float*)d_in[1];   // weight_theta [3,64,64]
    const float* wb   = (const float*)d_in[2];   // weight_bias  [64,64]
    const int*   nbh  = (const int*)  d_in[3];   // neighborhood [4,8,16384]
    const float* pos  = (const float*)d_in[4];   // positions  [4,3,16384]
    const float* bias = (const float*)d_in[5];   // bias [64]
    float* out = (float*)d_out;                  // [4,64,16384] fp32

    (void)in_sizes; (void)n_in; (void)out_size;

    cudaFuncSetAttribute(flexconv_main,
                         cudaFuncAttributeMaxDynamicSharedMemorySize, 114688);

    zero_kernel<<<4096, 256>>>();                       // 1,048,576 float4
    flexconv_main<<<Bv * (Nn / TILE), TPB, 114688>>>(feat, wt, wb, nbh, pos);
    finalize_kernel<<<Bv * (Nn / 64), 256>>>(out, bias);
}

// round 4
// speedup vs baseline: 1.2268x; 1.2268x over previous
#include <cuda_runtime.h>
#include <cstdint>
#include <cstddef>

// Problem constants
#define Bv    4
#define CINc  64
#define COUTc 64
#define Nn    16384
#define Kk    8
#define TILE  64
#define TPB   256
#define NTILES (Bv * (Nn / TILE))    // 1024
#define GRID_MAIN 296                // 2 persistent blocks per SM on 148 SMs
#define SMEM_BYTES 90112             // 22528 floats

// Channel-major scatter scratch: [B][N][COUT] as float4 chunks [B][N][16].
// Zero-initialized at module load; finalize_kernel re-zeroes it after reading,
// so it is always zero at kernel_launch entry (every call, every graph replay).
__device__ __align__(16) float4 g_scratch[(size_t)Bv * Nn * (COUTc / 4)];

// ---- PTX helpers -----------------------------------------------------------

// packed dual-FMA: 2x fp32 MAC per instruction (FFMA2 — ptxas won't auto-fuse)
__device__ __forceinline__ void fma2(unsigned long long &acc,
                                     unsigned long long a,
                                     unsigned long long b) {
    asm("fma.rn.f32x2 %0, %1, %2, %0;" : "+l"(acc) : "l"(a), "l"(b));
}
__device__ __forceinline__ unsigned long long pk2(float v) {
    unsigned long long r;
    asm("mov.b64 %0, {%1, %1};" : "=l"(r) : "f"(v));
    return r;
}
__device__ __forceinline__ float2 up2(unsigned long long v) {
    float2 r;
    asm("mov.b64 {%0, %1}, %2;" : "=f"(r.x), "=f"(r.y) : "l"(v));
    return r;
}
// 128-bit vector reduction (sm_90+): one op scatters 4 contiguous floats
__device__ __forceinline__ void red4(float* p, float a, float b, float c, float d) {
    asm volatile("red.global.add.v4.f32 [%0], {%1, %2, %3, %4};"
                 :: "l"(p), "f"(a), "f"(b), "f"(c), "f"(d) : "memory");
}

// ---- Kernel 1: fused GEMM + neighbor scatter --------------------------------
//
// Persistent blocks: grid=296, 256 threads, 2 blocks/SM (88KB smem each).
// W staged ONCE per block; each loop iteration handles one 64-point tile.
// smem: sW [64i][4d][64o] (64KB) | sF [64i][64p] (16KB)
//       sJ [8k][64p] (2KB)       | sD [3d][8k][64p] (6KB)   => 90112 B
// Thread mapping: group = tid/16 owns points p0..p0+3 (p0 = 4*group);
// lane-in-group lig owns output channels 4*lig..4*lig+3.

__global__ void __launch_bounds__(TPB, 2) flexconv_main(
    const float* __restrict__ feat,   // [B][Cin][N]
    const float* __restrict__ wt,     // [3][Cin][Cout]
    const float* __restrict__ wb,     // [Cin][Cout]
    const int*   __restrict__ nbh,    // [B][K][N]
    const float* __restrict__ pos)    // [B][3][N]
{
    extern __shared__ float sm[];
    float* sW = sm;                    // 16384 floats
    float* sF = sm + 16384;            // 4096 floats
    int*   sJ = (int*)(sm + 20480);    // 512 ints
    float* sD = sm + 20992;            // 1536 floats

    const int tid = threadIdx.x;

    // --- stage weights ONCE: theta [d][i][o] -> sW[i*256 + d*64 + o]
    #pragma unroll
    for (int t = tid; t < 3 * 64 * 64; t += TPB) {
        int d = t >> 12, i = (t >> 6) & 63, o = t & 63;
        sW[i * 256 + d * 64 + o] = wt[t];
    }
    // bias-weight goes in slot d=3
    #pragma unroll
    for (int t = tid; t < 64 * 64; t += TPB) {
        sW[(t >> 6) * 256 + 192 + (t & 63)] = wb[t];
    }

    const int grp = tid >> 4;
    const int lig = tid & 15;
    const int p0  = grp * 4;

    for (int tile = blockIdx.x; tile < NTILES; tile += gridDim.x) {
        const int b  = tile >> 8;                 // 256 tiles per batch
        const int n0 = (tile & 255) * TILE;

        // protect sF/sJ/sD from previous iteration's readers;
        // also covers the one-time W staging before first use.
        __syncthreads();

        // --- stage feature tile (float4): sF[i][p]
        {
            const float4* fsrc = (const float4*)(feat + (size_t)b * CINc * Nn + n0);
            #pragma unroll
            for (int t = tid; t < 64 * 16; t += TPB) {
                int i = t >> 4, p4 = t & 15;
                ((float4*)sF)[t] = fsrc[(size_t)i * (Nn / 4) + p4];
            }
        }
        // --- stage neighborhood indices + position deltas
        {
            const float* px = pos + (size_t)b * 3 * Nn;
            const float* py = px + Nn;
            const float* pz = py + Nn;
            const int*   nb = nbh + (size_t)b * Kk * Nn + n0;
            #pragma unroll
            for (int t = tid; t < Kk * TILE; t += TPB) {
                int k = t >> 6, p = t & 63;
                int n = n0 + p;
                int j = nb[(size_t)k * Nn + p];
                sJ[t]        = j;
                sD[t]        = px[j] - px[n];
                sD[512 + t]  = py[j] - py[n];
                sD[1024 + t] = pz[j] - pz[n];
            }
        }
        __syncthreads();

        // accumulators: [point q][dim d (x,y,z,biasw)][2x packed f32]
        unsigned long long acc[4][4][2];
        #pragma unroll
        for (int q = 0; q < 4; q++)
            #pragma unroll
            for (int d = 0; d < 4; d++) { acc[q][d][0] = 0ull; acc[q][d][1] = 0ull; }

        // --- dense phase: ft[d][o] = sum_i W[d][i][o] * f[i][n], 4 points at once
        #pragma unroll 2
        for (int i = 0; i < 64; i++) {
            const ulonglong2* wrow = (const ulonglong2*)(sW + i * 256);
            ulonglong2 w0 = wrow[lig];        // d=0 (x), channels 4*lig..+3
            ulonglong2 w1 = wrow[16 + lig];   // d=1 (y)
            ulonglong2 w2 = wrow[32 + lig];   // d=2 (z)
            ulonglong2 w3 = wrow[48 + lig];   // d=3 (bias weight)
            float4 fv = *(const float4*)(sF + i * TILE + p0);
            unsigned long long f[4] = { pk2(fv.x), pk2(fv.y), pk2(fv.z), pk2(fv.w) };
            #pragma unroll
            for (int q = 0; q < 4; q++) {
                fma2(acc[q][0][0], w0.x, f[q]); fma2(acc[q][0][1], w0.y, f[q]);
                fma2(acc[q][1][0], w1.x, f[q]); fma2(acc[q][1][1], w1.y, f[q]);
                fma2(acc[q][2][0], w2.x, f[q]); fma2(acc[q][2][1], w2.y, f[q]);
                fma2(acc[q][3][0], w3.x, f[q]); fma2(acc[q][3][1], w3.y, f[q]);
            }
        }

        // --- scatter phase: contrib[o] = fb[o] + dx*ftx[o] + dy*fty[o] + dz*ftz[o]
        // lanes 0-15 of a warp share p (same j): 16 consecutive lig -> one
        // contiguous 256B red burst per half-warp.
        #pragma unroll
        for (int q = 0; q < 4; q++) {
            int p = p0 + q;
            float2 x01 = up2(acc[q][0][0]), x23 = up2(acc[q][0][1]);
            float2 y01 = up2(acc[q][1][0]), y23 = up2(acc[q][1][1]);
            float2 z01 = up2(acc[q][2][0]), z23 = up2(acc[q][2][1]);
            float2 w01 = up2(acc[q][3][0]), w23 = up2(acc[q][3][1]);
            #pragma unroll
            for (int k = 0; k < 8; k++) {
                int   j  = sJ[k * TILE + p];
                float dx = sD[k * TILE + p];
                float dy = sD[512 + k * TILE + p];
                float dz = sD[1024 + k * TILE + p];
                float v0 = w01.x + dx * x01.x + dy * y01.x + dz * z01.x;
                float v1 = w01.y + dx * x01.y + dy * y01.y + dz * z01.y;
                float v2 = w23.x + dx * x23.x + dy * y23.x + dz * z23.x;
                float v3 = w23.y + dx * x23.y + dy * y23.y + dz * z23.y;
                float* dst = (float*)&g_scratch[((size_t)b * Nn + j) * 16 + lig];
                red4(dst, v0, v1, v2, v3);
            }
        }
    }
}

// ---- Kernel 2: transpose scratch [B][N][Cout] -> out [B][Cout][N], add bias,
//      and re-zero scratch for the next call / graph replay. ------------------

__global__ void finalize_kernel(float* __restrict__ out, const float* __restrict__ bias) {
    __shared__ float s[64][65];
    const int b   = blockIdx.x >> 8;          // 256 tiles of 64 points per batch
    const int n0  = (blockIdx.x & 255) * 64;
    const int tid = threadIdx.x;              // 256 threads

    float4* src = (float4*)g_scratch + ((size_t)b * Nn + n0) * 16;
    #pragma unroll
    for (int r = 0; r < 4; r++) {
        int idx = r * 256 + tid;              // linear over [p(64)][c4(16)]
        float4 v = src[idx];
        src[idx] = make_float4(0.f, 0.f, 0.f, 0.f);   // re-zero for next call
        int p = idx >> 4, c = (idx & 15) * 4;
        s[p][c] = v.x; s[p][c + 1] = v.y; s[p][c + 2] = v.z; s[p][c + 3] = v.w;
    }
    __syncthreads();
    #pragma unroll
    for (int r = 0; r < 4; r++) {
        int idx = r * 256 + tid;              // [o(64)][p4(16)]
        int o = idx >> 4, p4 = (idx & 15) * 4;
        float bo = __ldg(bias + o);
        float4 v = make_float4(s[p4][o] + bo, s[p4 + 1][o] + bo,
                               s[p4 + 2][o] + bo, s[p4 + 3][o] + bo);
        *(float4*)(out + ((size_t)b * 64 + o) * Nn + n0 + p4) = v;
    }
}

// ---- launch -----------------------------------------------------------------

extern "C" void kernel_launch(void* const* d_in, const int* in_sizes, int n_in,
                              void* d_out, int out_size) {
    const float* feat = (const float*)d_in[0];   // features     [4,64,16384]
    const float* wt   = (const float*)d_in[1];   // weight_theta [3,64,64]
    const float* wb   = (const float*)d_in[2];   // weight_bias  [64,64]
    const int*   nbh  = (const int*)  d_in[3];   // neighborhood [4,8,16384]
    const float* pos  = (const float*)d_in[4];   // positions    [4,3,16384]
    const float* bias = (const float*)d_in[5];   // bias [64]
    float* out = (float*)d_out;                  // [4,64,16384] fp32

    (void)in_sizes; (void)n_in; (void)out_size;

    cudaFuncSetAttribute(flexconv_main,
                         cudaFuncAttributeMaxDynamicSharedMemorySize, SMEM_BYTES);

    flexconv_main<<<GRID_MAIN, TPB, SMEM_BYTES>>>(feat, wt, wb, nbh, pos);
    finalize_kernel<<<Bv * (Nn / 64), 256>>>(out, bias);
}